// round 12
// baseline (speedup 1.0000x reference)
#include <cuda_runtime.h>
#include <math.h>

#define BB    4
#define SSEQ  4096
#define IND   1024
#define OUTD  1024
#define EE    8
#define LSCALE 512.0f

// ---- scratch (device globals; allocation is forbidden) ----
__device__ float    g_seg[BB * IND];   // 16 KB : per-batch column sums (zeroed after use)
__device__ float    g_coef[BB * 2];
__device__ int      g_idx[BB * 2];
__device__ unsigned g_arrive;          // P1 completion counter (reset in tail)

typedef unsigned long long u64;

__device__ __forceinline__ void fma2(u64& d, u64 a, u64 b) {
    asm("fma.rn.f32x2 %0, %1, %2, %0;" : "+l"(d) : "l"(a), "l"(b));
}
__device__ __forceinline__ float lo2(u64 v) { return __uint_as_float((unsigned)(v & 0xffffffffull)); }
__device__ __forceinline__ float hi2(u64 v) { return __uint_as_float((unsigned)(v >> 32)); }

// streaming 16B store (out is never re-read)
__device__ __forceinline__ void stcs4(float* p, float4 v) {
    asm volatile("st.global.cs.v4.f32 [%0], {%1, %2, %3, %4};"
                 :: "l"(p), "f"(v.x), "f"(v.y), "f"(v.z), "f"(v.w));
}

// ------------------------------------------------------------------
// P1: seg[b][col] = sum_s x[b,s,col]  (streaming read; x stays in L2
// for P2). grid=512 (32 rows each), 256 thr. Fused gating tail in
// the last CTA (acq_rel arrive; no L1 flush).
// ------------------------------------------------------------------
__global__ void __launch_bounds__(256) p1_seg(const float* __restrict__ x,
                                              const float* __restrict__ gate_w,
                                              const float* __restrict__ gate_b) {
    const int tid = threadIdx.x;
    const int b       = blockIdx.x >> 7;            // 128 blocks per batch
    const int rowbase = (blockIdx.x & 127) * 32;

    const float* xp = x + ((size_t)b * SSEQ + rowbase) * IND + tid * 4;
    float4 acc = make_float4(0.f, 0.f, 0.f, 0.f);
    #pragma unroll 8
    for (int r = 0; r < 32; ++r) {
        float4 v = *(const float4*)(xp + (size_t)r * IND);
        acc.x += v.x; acc.y += v.y; acc.z += v.z; acc.w += v.w;
    }
    {
        float* dst = &g_seg[b * IND + tid * 4];
        atomicAdd(dst + 0, acc.x);
        atomicAdd(dst + 1, acc.y);
        atomicAdd(dst + 2, acc.z);
        atomicAdd(dst + 3, acc.w);
    }

    // ====== fused gating: last CTA (acq_rel arrive; proven) ======
    __shared__ unsigned s_last;
    __syncthreads();
    if (tid == 0) {
        unsigned old;
        asm volatile("atom.acq_rel.gpu.global.add.u32 %0, [%1], 1;"
                     : "=r"(old) : "l"(&g_arrive) : "memory");
        s_last = (old == (unsigned)(gridDim.x - 1)) ? 1u : 0u;
    }
    __syncthreads();
    if (!s_last) return;

    __shared__ float dots[BB * EE];
    {
        int pair = tid >> 3, l8 = tid & 7;          // 32 (b,e) pairs x 8 threads
        int bb = pair >> 3, e = pair & 7;
        float s = 0.f;
        #pragma unroll 8
        for (int k = l8 * 4; k < IND; k += 32) {
            float4 a = *(const float4*)&g_seg[bb * IND + k];
            float4 g = *(const float4*)&gate_w[e * IND + k];
            s += a.x * g.x + a.y * g.y + a.z * g.z + a.w * g.w;
        }
        #pragma unroll
        for (int o = 4; o; o >>= 1) s += __shfl_xor_sync(0xffffffffu, s, o);
        if (l8 == 0) dots[pair] = s * (1.0f / (float)SSEQ) + gate_b[e];
    }
    __syncthreads();

    // zero g_seg for the next graph replay (1024 float4, 4/thread)
    #pragma unroll
    for (int j = 0; j < 4; ++j)
        ((float4*)g_seg)[tid + j * 256] = make_float4(0.f, 0.f, 0.f, 0.f);

    if (tid < BB) {
        int bb = tid;
        float l[EE]; float mx = -1e30f;
        #pragma unroll
        for (int i = 0; i < EE; ++i) { l[i] = dots[bb * EE + i]; mx = fmaxf(mx, l[i]); }
        float sum = 0.f;
        #pragma unroll
        for (int i = 0; i < EE; ++i) { l[i] = expf(l[i] - mx); sum += l[i]; }
        int i0 = 0;
        #pragma unroll
        for (int i = 1; i < EE; ++i) if (l[i] > l[i0]) i0 = i;     // ties -> lowest idx
        int i1 = (i0 == 0) ? 1 : 0;
        #pragma unroll
        for (int i = 0; i < EE; ++i) if (i != i0 && l[i] > l[i1]) i1 = i;
        g_idx[bb * 2] = i0;  g_idx[bb * 2 + 1] = i1;
        float f = LSCALE / sum;
        g_coef[bb * 2]     = l[i0] * f;
        g_coef[bb * 2 + 1] = l[i1] * f;
    }
    if (tid == 0) g_arrive = 0;                     // reset for next replay
}

// ------------------------------------------------------------------
// P2: fused select + project (x from L2). Chunk loop unroll 2:
// 8 LDG.128 in flight/warp is enough for ~234cyc L2 latency, and
// the register footprint drops to ~50 -> 5 CTAs/SM (occ ~60%).
// ------------------------------------------------------------------
#define TOKB 32
#define TPW  4

__global__ void __launch_bounds__(256, 5) p2_out(const float* __restrict__ x,
                                                 const float* __restrict__ lora_A,
                                                 const float* __restrict__ lora_B,
                                                 float* __restrict__ out) {
    __shared__ float  A2[2 * IND];     // 8 KB : selected experts' A rows
    __shared__ float2 cs[TOKB];

    const int tid  = threadIdx.x;
    const int w    = tid >> 5;
    const int lane = tid & 31;
    const int b       = blockIdx.x >> 7;            // 128 blocks per batch
    const int tokbase = (blockIdx.x & 127) * TOKB;

    const int e0 = g_idx[b * 2], e1 = g_idx[b * 2 + 1];
    const float w0 = g_coef[b * 2], w1 = g_coef[b * 2 + 1];

    // stage A_e0, A_e1 (coalesced float4 copies)
    {
        float4 a0 = *(const float4*)&lora_A[e0 * IND + tid * 4];
        float4 a1 = *(const float4*)&lora_A[e1 * IND + tid * 4];
        *(float4*)&A2[tid * 4]       = a0;
        *(float4*)&A2[IND + tid * 4] = a1;
    }
    // B rows register-resident (1 float4 per expert per thread)
    float4 B0 = *(const float4*)&lora_B[e0 * OUTD + tid * 4];
    float4 B1 = *(const float4*)&lora_B[e1 * OUTD + tid * 4];
    __syncthreads();

    // ---- phase A: 2 selected dots for this warp's 4 tokens ----
    u64 acc0[TPW], acc1[TPW];
    #pragma unroll
    for (int t = 0; t < TPW; ++t) { acc0[t] = 0ull; acc1[t] = 0ull; }

    const float* xw = x + ((size_t)(b * SSEQ + tokbase + w * TPW)) * IND;

    #pragma unroll 2
    for (int c = 0; c < 8; ++c) {
        const int koff = c * 128 + lane * 4;
        double2 a0v = *(const double2*)&A2[koff];
        double2 a1v = *(const double2*)&A2[IND + koff];
        u64 a0lo = __double_as_longlong(a0v.x), a0hi = __double_as_longlong(a0v.y);
        u64 a1lo = __double_as_longlong(a1v.x), a1hi = __double_as_longlong(a1v.y);
        #pragma unroll
        for (int t = 0; t < TPW; ++t) {
            double2 xv = *(const double2*)(xw + (size_t)t * IND + koff);
            u64 xlo = __double_as_longlong(xv.x);
            u64 xhi = __double_as_longlong(xv.y);
            fma2(acc0[t], xlo, a0lo);
            fma2(acc0[t], xhi, a0hi);
            fma2(acc1[t], xlo, a1lo);
            fma2(acc1[t], xhi, a1hi);
        }
    }

    #pragma unroll
    for (int t = 0; t < TPW; ++t) {
        float h0 = lo2(acc0[t]) + hi2(acc0[t]);
        float h1 = lo2(acc1[t]) + hi2(acc1[t]);
        #pragma unroll
        for (int off = 16; off; off >>= 1) {
            h0 += __shfl_xor_sync(0xffffffffu, h0, off);
            h1 += __shfl_xor_sync(0xffffffffu, h1, off);
        }
        if (lane == 0) cs[w * TPW + t] = make_float2(w0 * h0, w1 * h1);
    }
    __syncthreads();

    // ---- phase B: proven store loop ----
    float* ob = out + ((size_t)b * SSEQ + tokbase) * OUTD + tid * 4;
    #pragma unroll 4
    for (int i = 0; i < TOKB; ++i) {
        float2 cc = cs[i];
        float4 v;
        v.x = cc.x * B0.x + cc.y * B1.x;
        v.y = cc.x * B0.y + cc.y * B1.y;
        v.z = cc.x * B0.z + cc.y * B1.z;
        v.w = cc.x * B0.w + cc.y * B1.w;
        stcs4(ob + (size_t)i * OUTD, v);
    }
}

// ------------------------------------------------------------------
extern "C" void kernel_launch(void* const* d_in, const int* in_sizes, int n_in,
                              void* d_out, int out_size) {
    const float* x      = (const float*)d_in[0];
    const float* lora_A = (const float*)d_in[1];
    const float* lora_B = (const float*)d_in[2];
    const float* gate_w = (const float*)d_in[3];
    const float* gate_b = (const float*)d_in[4];
    float* out = (float*)d_out;

    p1_seg<<<BB * (SSEQ / 32), 256>>>(x, gate_w, gate_b);
    p2_out<<<BB * (SSEQ / TOKB), 256>>>(x, lora_A, lora_B, out);
}

// round 13
// speedup vs baseline: 1.1549x; 1.1549x over previous
#include <cuda_runtime.h>
#include <math.h>

#define BB    4
#define SSEQ  4096
#define IND   1024
#define OUTD  1024
#define EE    8
#define LSCALE 512.0f

// ---- scratch (device globals; allocation is forbidden) ----
__device__ float    g_seg[BB * IND];   // 16 KB : per-batch column sums (zeroed after use)
__device__ float    g_coef[BB * 2];
__device__ int      g_idx[BB * 2];
__device__ unsigned g_arrive;          // P1 completion counter (reset in tail)

typedef unsigned long long u64;

__device__ __forceinline__ void fma2(u64& d, u64 a, u64 b) {
    asm("fma.rn.f32x2 %0, %1, %2, %0;" : "+l"(d) : "l"(a), "l"(b));
}
__device__ __forceinline__ float lo2(u64 v) { return __uint_as_float((unsigned)(v & 0xffffffffull)); }
__device__ __forceinline__ float hi2(u64 v) { return __uint_as_float((unsigned)(v >> 32)); }

// streaming 16B store (out is never re-read)
__device__ __forceinline__ void stcs4(float* p, float4 v) {
    asm volatile("st.global.cs.v4.f32 [%0], {%1, %2, %3, %4};"
                 :: "l"(p), "f"(v.x), "f"(v.y), "f"(v.z), "f"(v.w));
}

// ------------------------------------------------------------------
// P1: seg[b][col] = sum_s x[b,s,col]  (streaming read; x stays in L2
// for P2). grid=512 (32 rows each), 256 thr. Fused gating tail in
// the last CTA (acq_rel arrive; no L1 flush). PROVEN — unchanged.
// ------------------------------------------------------------------
__global__ void __launch_bounds__(256) p1_seg(const float* __restrict__ x,
                                              const float* __restrict__ gate_w,
                                              const float* __restrict__ gate_b) {
    const int tid = threadIdx.x;
    const int b       = blockIdx.x >> 7;            // 128 blocks per batch
    const int rowbase = (blockIdx.x & 127) * 32;

    const float* xp = x + ((size_t)b * SSEQ + rowbase) * IND + tid * 4;
    float4 acc = make_float4(0.f, 0.f, 0.f, 0.f);
    #pragma unroll 8
    for (int r = 0; r < 32; ++r) {
        float4 v = *(const float4*)(xp + (size_t)r * IND);
        acc.x += v.x; acc.y += v.y; acc.z += v.z; acc.w += v.w;
    }
    {
        float* dst = &g_seg[b * IND + tid * 4];
        atomicAdd(dst + 0, acc.x);
        atomicAdd(dst + 1, acc.y);
        atomicAdd(dst + 2, acc.z);
        atomicAdd(dst + 3, acc.w);
    }

    // ====== fused gating: last CTA (acq_rel arrive; proven) ======
    __shared__ unsigned s_last;
    __syncthreads();
    if (tid == 0) {
        unsigned old;
        asm volatile("atom.acq_rel.gpu.global.add.u32 %0, [%1], 1;"
                     : "=r"(old) : "l"(&g_arrive) : "memory");
        s_last = (old == (unsigned)(gridDim.x - 1)) ? 1u : 0u;
    }
    __syncthreads();
    if (!s_last) return;

    __shared__ float dots[BB * EE];
    {
        int pair = tid >> 3, l8 = tid & 7;          // 32 (b,e) pairs x 8 threads
        int bb = pair >> 3, e = pair & 7;
        float s = 0.f;
        #pragma unroll 8
        for (int k = l8 * 4; k < IND; k += 32) {
            float4 a = *(const float4*)&g_seg[bb * IND + k];
            float4 g = *(const float4*)&gate_w[e * IND + k];
            s += a.x * g.x + a.y * g.y + a.z * g.z + a.w * g.w;
        }
        #pragma unroll
        for (int o = 4; o; o >>= 1) s += __shfl_xor_sync(0xffffffffu, s, o);
        if (l8 == 0) dots[pair] = s * (1.0f / (float)SSEQ) + gate_b[e];
    }
    __syncthreads();

    // zero g_seg for the next graph replay (1024 float4, 4/thread)
    #pragma unroll
    for (int j = 0; j < 4; ++j)
        ((float4*)g_seg)[tid + j * 256] = make_float4(0.f, 0.f, 0.f, 0.f);

    if (tid < BB) {
        int bb = tid;
        float l[EE]; float mx = -1e30f;
        #pragma unroll
        for (int i = 0; i < EE; ++i) { l[i] = dots[bb * EE + i]; mx = fmaxf(mx, l[i]); }
        float sum = 0.f;
        #pragma unroll
        for (int i = 0; i < EE; ++i) { l[i] = expf(l[i] - mx); sum += l[i]; }
        int i0 = 0;
        #pragma unroll
        for (int i = 1; i < EE; ++i) if (l[i] > l[i0]) i0 = i;     // ties -> lowest idx
        int i1 = (i0 == 0) ? 1 : 0;
        #pragma unroll
        for (int i = 0; i < EE; ++i) if (i != i0 && l[i] > l[i1]) i1 = i;
        g_idx[bb * 2] = i0;  g_idx[bb * 2 + 1] = i1;
        float f = LSCALE / sum;
        g_coef[bb * 2]     = l[i0] * f;
        g_coef[bb * 2 + 1] = l[i1] * f;
    }
    if (tid == 0) g_arrive = 0;                     // reset for next replay
}

// ------------------------------------------------------------------
// P2: fused select + project (x from L2) — SINGLE-WAVE variant.
// 4 CTAs/SM x 148 SMs = 592 >= 512 CTAs -> one wave.
// Chunk loop unroll 4 (16 LDG.128 in flight/warp); B loads deferred
// to phase B so phase-A live regs fit the 64-reg budget.
// ------------------------------------------------------------------
#define TOKB 32
#define TPW  4

__global__ void __launch_bounds__(256, 4) p2_out(const float* __restrict__ x,
                                                 const float* __restrict__ lora_A,
                                                 const float* __restrict__ lora_B,
                                                 float* __restrict__ out) {
    __shared__ float  A2[2 * IND];     // 8 KB : selected experts' A rows
    __shared__ float2 cs[TOKB];

    const int tid  = threadIdx.x;
    const int w    = tid >> 5;
    const int lane = tid & 31;
    const int b       = blockIdx.x >> 7;            // 128 blocks per batch
    const int tokbase = (blockIdx.x & 127) * TOKB;

    const int e0 = g_idx[b * 2], e1 = g_idx[b * 2 + 1];
    const float w0 = g_coef[b * 2], w1 = g_coef[b * 2 + 1];

    // stage A_e0, A_e1 (coalesced float4 copies)
    {
        float4 a0 = *(const float4*)&lora_A[e0 * IND + tid * 4];
        float4 a1 = *(const float4*)&lora_A[e1 * IND + tid * 4];
        *(float4*)&A2[tid * 4]       = a0;
        *(float4*)&A2[IND + tid * 4] = a1;
    }
    __syncthreads();

    // ---- phase A: 2 selected dots for this warp's 4 tokens ----
    u64 acc0[TPW], acc1[TPW];
    #pragma unroll
    for (int t = 0; t < TPW; ++t) { acc0[t] = 0ull; acc1[t] = 0ull; }

    const float* xw = x + ((size_t)(b * SSEQ + tokbase + w * TPW)) * IND;

    #pragma unroll 4
    for (int c = 0; c < 8; ++c) {
        const int koff = c * 128 + lane * 4;
        double2 a0v = *(const double2*)&A2[koff];
        double2 a1v = *(const double2*)&A2[IND + koff];
        u64 a0lo = __double_as_longlong(a0v.x), a0hi = __double_as_longlong(a0v.y);
        u64 a1lo = __double_as_longlong(a1v.x), a1hi = __double_as_longlong(a1v.y);
        #pragma unroll
        for (int t = 0; t < TPW; ++t) {
            double2 xv = *(const double2*)(xw + (size_t)t * IND + koff);
            u64 xlo = __double_as_longlong(xv.x);
            u64 xhi = __double_as_longlong(xv.y);
            fma2(acc0[t], xlo, a0lo);
            fma2(acc0[t], xhi, a0hi);
            fma2(acc1[t], xlo, a1lo);
            fma2(acc1[t], xhi, a1hi);
        }
    }

    #pragma unroll
    for (int t = 0; t < TPW; ++t) {
        float h0 = lo2(acc0[t]) + hi2(acc0[t]);
        float h1 = lo2(acc1[t]) + hi2(acc1[t]);
        #pragma unroll
        for (int off = 16; off; off >>= 1) {
            h0 += __shfl_xor_sync(0xffffffffu, h0, off);
            h1 += __shfl_xor_sync(0xffffffffu, h1, off);
        }
        if (lane == 0) cs[w * TPW + t] = make_float2(w0 * h0, w1 * h1);
    }

    // B rows register-resident — loaded AFTER phase A (not live above)
    float4 B0 = *(const float4*)&lora_B[e0 * OUTD + tid * 4];
    float4 B1 = *(const float4*)&lora_B[e1 * OUTD + tid * 4];
    __syncthreads();

    // ---- phase B: proven store loop ----
    float* ob = out + ((size_t)b * SSEQ + tokbase) * OUTD + tid * 4;
    #pragma unroll 4
    for (int i = 0; i < TOKB; ++i) {
        float2 cc = cs[i];
        float4 v;
        v.x = cc.x * B0.x + cc.y * B1.x;
        v.y = cc.x * B0.y + cc.y * B1.y;
        v.z = cc.x * B0.z + cc.y * B1.z;
        v.w = cc.x * B0.w + cc.y * B1.w;
        stcs4(ob + (size_t)i * OUTD, v);
    }
}

// ------------------------------------------------------------------
extern "C" void kernel_launch(void* const* d_in, const int* in_sizes, int n_in,
                              void* d_out, int out_size) {
    const float* x      = (const float*)d_in[0];
    const float* lora_A = (const float*)d_in[1];
    const float* lora_B = (const float*)d_in[2];
    const float* gate_w = (const float*)d_in[3];
    const float* gate_b = (const float*)d_in[4];
    float* out = (float*)d_out;

    p1_seg<<<BB * (SSEQ / 32), 256>>>(x, gate_w, gate_b);
    p2_out<<<BB * (SSEQ / TOKB), 256>>>(x, lora_A, lora_B, out);
}

// round 14
// speedup vs baseline: 1.1682x; 1.0115x over previous
#include <cuda_runtime.h>
#include <math.h>

#define BB    4
#define SSEQ  4096
#define IND   1024
#define OUTD  1024
#define EE    8
#define LSCALE 512.0f
#define GRID  512

// ---- scratch (device globals; allocation is forbidden) ----
__device__ float    g_seg[BB * IND];   // 16 KB : per-batch column sums (zeroed after use)
__device__ float    g_coef[BB * 2];
__device__ int      g_idx[BB * 2];
__device__ unsigned g_arrive;          // stage-1 arrival counter (reset by gating CTA)
__device__ unsigned g_flag;            // gating-done flag (reset by last finisher)
__device__ unsigned g_done;            // stage-2 completion counter

typedef unsigned long long u64;

__device__ __forceinline__ void fma2(u64& d, u64 a, u64 b) {
    asm("fma.rn.f32x2 %0, %1, %2, %0;" : "+l"(d) : "l"(a), "l"(b));
}
__device__ __forceinline__ float lo2(u64 v) { return __uint_as_float((unsigned)(v & 0xffffffffull)); }
__device__ __forceinline__ float hi2(u64 v) { return __uint_as_float((unsigned)(v >> 32)); }

__device__ __forceinline__ void stcs4(float* p, float4 v) {
    asm volatile("st.global.cs.v4.f32 [%0], {%1, %2, %3, %4};"
                 :: "l"(p), "f"(v.x), "f"(v.y), "f"(v.z), "f"(v.w));
}

// ------------------------------------------------------------------
// Fused persistent kernel. 512 CTAs, 256 thr, HARD 64-reg cap via
// launch_bounds(256,4): 4 CTAs/SM x 148 SMs = 592 >= 512, so every
// CTA is wave-1 resident -> the flag spin cannot deadlock.
//   stage 1: column sums of this CTA's 32 token rows  (DRAM read)
//   barrier: acq_rel arrive; last CTA does gating, releases g_flag
//   stage 2: R13-proven select+project on the SAME rows (L1/L2 hot)
// ------------------------------------------------------------------
#define TOKB 32
#define TPW  4

__global__ void __launch_bounds__(256, 4) fused_moe(const float* __restrict__ x,
                                                    const float* __restrict__ lora_A,
                                                    const float* __restrict__ lora_B,
                                                    const float* __restrict__ gate_w,
                                                    const float* __restrict__ gate_b,
                                                    float* __restrict__ out) {
    __shared__ float    A2[2 * IND];    // 8 KB : selected experts' A rows
    __shared__ float2   cs[TOKB];
    __shared__ float    dots[BB * EE];
    __shared__ unsigned s_last;
    __shared__ int2     s_ix;
    __shared__ float2   s_cf;

    const int tid  = threadIdx.x;
    const int w    = tid >> 5;
    const int lane = tid & 31;
    const int b       = blockIdx.x >> 7;            // 128 blocks per batch
    const int tokbase = (blockIdx.x & 127) * TOKB;

    // ================= stage 1: column sums (x -> L1/L2) =================
    {
        const float* xp = x + ((size_t)b * SSEQ + tokbase) * IND + tid * 4;
        float4 a4 = make_float4(0.f, 0.f, 0.f, 0.f);
        #pragma unroll 8
        for (int r = 0; r < TOKB; ++r) {
            float4 v = *(const float4*)(xp + (size_t)r * IND);
            a4.x += v.x; a4.y += v.y; a4.z += v.z; a4.w += v.w;
        }
        float* dst = &g_seg[b * IND + tid * 4];
        atomicAdd(dst + 0, a4.x);
        atomicAdd(dst + 1, a4.y);
        atomicAdd(dst + 2, a4.z);
        atomicAdd(dst + 3, a4.w);
    }

    // ================= arrive; last CTA gates; others spin ===============
    __syncthreads();
    if (tid == 0) {
        unsigned old;
        asm volatile("atom.acq_rel.gpu.global.add.u32 %0, [%1], 1;"
                     : "=r"(old) : "l"(&g_arrive) : "memory");
        s_last = (old == (unsigned)(GRID - 1)) ? 1u : 0u;
    }
    __syncthreads();

    if (s_last) {
        // ---- gating (proven tail) ----
        {
            int pair = tid >> 3, l8 = tid & 7;      // 32 (b,e) pairs x 8 threads
            int bb = pair >> 3, e = pair & 7;
            float s = 0.f;
            #pragma unroll 8
            for (int k = l8 * 4; k < IND; k += 32) {
                float4 a = *(const float4*)&g_seg[bb * IND + k];
                float4 g = *(const float4*)&gate_w[e * IND + k];
                s += a.x * g.x + a.y * g.y + a.z * g.z + a.w * g.w;
            }
            #pragma unroll
            for (int o = 4; o; o >>= 1) s += __shfl_xor_sync(0xffffffffu, s, o);
            if (l8 == 0) dots[pair] = s * (1.0f / (float)SSEQ) + gate_b[e];
        }
        __syncthreads();

        // zero g_seg for the next graph replay
        #pragma unroll
        for (int j = 0; j < 4; ++j)
            ((float4*)g_seg)[tid + j * 256] = make_float4(0.f, 0.f, 0.f, 0.f);

        if (tid < BB) {
            int bb = tid;
            float l[EE]; float mx = -1e30f;
            #pragma unroll
            for (int i = 0; i < EE; ++i) { l[i] = dots[bb * EE + i]; mx = fmaxf(mx, l[i]); }
            float sum = 0.f;
            #pragma unroll
            for (int i = 0; i < EE; ++i) { l[i] = expf(l[i] - mx); sum += l[i]; }
            int i0 = 0;
            #pragma unroll
            for (int i = 1; i < EE; ++i) if (l[i] > l[i0]) i0 = i;   // ties -> lowest idx
            int i1 = (i0 == 0) ? 1 : 0;
            #pragma unroll
            for (int i = 0; i < EE; ++i) if (i != i0 && l[i] > l[i1]) i1 = i;
            g_idx[bb * 2] = i0;  g_idx[bb * 2 + 1] = i1;
            float f = LSCALE / sum;
            g_coef[bb * 2]     = l[i0] * f;
            g_coef[bb * 2 + 1] = l[i1] * f;
        }
        if (tid == 0) g_arrive = 0;                 // safe: all CTAs already arrived
        __syncthreads();                            // coef/idx written before release
        if (tid == 0)
            asm volatile("st.release.gpu.global.u32 [%0], %1;"
                         :: "l"(&g_flag), "r"(1u) : "memory");
    } else {
        if (tid == 0) {
            unsigned f = 0;
            do {
                __nanosleep(128);
                asm volatile("ld.acquire.gpu.global.u32 %0, [%1];"
                             : "=r"(f) : "l"(&g_flag) : "memory");
            } while (f == 0);
        }
    }
    __syncthreads();

    // broadcast gate results via shared (tid0 holds the acquire edge)
    if (tid == 0) {
        s_ix = *(const int2*)&g_idx[b * 2];
        s_cf = *(const float2*)&g_coef[b * 2];
    }
    __syncthreads();
    const int   e0 = s_ix.x, e1 = s_ix.y;
    const float w0 = s_cf.x, w1 = s_cf.y;

    // ================= stage 2: select + project (R13-proven) ============
    // stage A_e0, A_e1
    {
        float4 a0 = *(const float4*)&lora_A[e0 * IND + tid * 4];
        float4 a1 = *(const float4*)&lora_A[e1 * IND + tid * 4];
        *(float4*)&A2[tid * 4]       = a0;
        *(float4*)&A2[IND + tid * 4] = a1;
    }
    __syncthreads();

    u64 acc0[TPW], acc1[TPW];
    #pragma unroll
    for (int t = 0; t < TPW; ++t) { acc0[t] = 0ull; acc1[t] = 0ull; }

    const float* xw = x + ((size_t)(b * SSEQ + tokbase + w * TPW)) * IND;

    #pragma unroll 4
    for (int c = 0; c < 8; ++c) {
        const int koff = c * 128 + lane * 4;
        double2 a0v = *(const double2*)&A2[koff];
        double2 a1v = *(const double2*)&A2[IND + koff];
        u64 a0lo = __double_as_longlong(a0v.x), a0hi = __double_as_longlong(a0v.y);
        u64 a1lo = __double_as_longlong(a1v.x), a1hi = __double_as_longlong(a1v.y);
        #pragma unroll
        for (int t = 0; t < TPW; ++t) {
            double2 xv = *(const double2*)(xw + (size_t)t * IND + koff);
            u64 xlo = __double_as_longlong(xv.x);
            u64 xhi = __double_as_longlong(xv.y);
            fma2(acc0[t], xlo, a0lo);
            fma2(acc0[t], xhi, a0hi);
            fma2(acc1[t], xlo, a1lo);
            fma2(acc1[t], xhi, a1hi);
        }
    }

    #pragma unroll
    for (int t = 0; t < TPW; ++t) {
        float h0 = lo2(acc0[t]) + hi2(acc0[t]);
        float h1 = lo2(acc1[t]) + hi2(acc1[t]);
        #pragma unroll
        for (int off = 16; off; off >>= 1) {
            h0 += __shfl_xor_sync(0xffffffffu, h0, off);
            h1 += __shfl_xor_sync(0xffffffffu, h1, off);
        }
        if (lane == 0) cs[w * TPW + t] = make_float2(w0 * h0, w1 * h1);
    }

    // B rows register-resident — loaded after phase A
    float4 B0 = *(const float4*)&lora_B[e0 * OUTD + tid * 4];
    float4 B1 = *(const float4*)&lora_B[e1 * OUTD + tid * 4];
    __syncthreads();

    float* ob = out + ((size_t)b * SSEQ + tokbase) * OUTD + tid * 4;
    #pragma unroll 4
    for (int i = 0; i < TOKB; ++i) {
        float2 cc = cs[i];
        float4 v;
        v.x = cc.x * B0.x + cc.y * B1.x;
        v.y = cc.x * B0.y + cc.y * B1.y;
        v.z = cc.x * B0.z + cc.y * B1.z;
        v.w = cc.x * B0.w + cc.y * B1.w;
        stcs4(ob + (size_t)i * OUTD, v);
    }

    // ---- reset g_flag for the next graph replay (last finisher) ----
    __syncthreads();
    if (tid == 0) {
        unsigned old;
        asm volatile("atom.acq_rel.gpu.global.add.u32 %0, [%1], 1;"
                     : "=r"(old) : "l"(&g_done) : "memory");
        if (old == (unsigned)(GRID - 1)) {
            g_flag = 0;
            g_done = 0;
        }
    }
}

// ------------------------------------------------------------------
extern "C" void kernel_launch(void* const* d_in, const int* in_sizes, int n_in,
                              void* d_out, int out_size) {
    const float* x      = (const float*)d_in[0];
    const float* lora_A = (const float*)d_in[1];
    const float* lora_B = (const float*)d_in[2];
    const float* gate_w = (const float*)d_in[3];
    const float* gate_b = (const float*)d_in[4];
    float* out = (float*)d_out;

    fused_moe<<<GRID, 256>>>(x, lora_A, lora_B, gate_w, gate_b, out);
}

// round 15
// speedup vs baseline: 1.3575x; 1.1621x over previous
#include <cuda_runtime.h>
#include <math.h>

#define BB    4
#define SSEQ  4096
#define IND   1024
#define OUTD  1024
#define EE    8
#define LSCALE 512.0f
#define GRID  512
#define CPB   128            // CTAs per batch

// ---- scratch (device globals; allocation is forbidden) ----
__device__ float    g_seg[BB * IND];   // 16 KB : per-batch column sums (zeroed by gater)
__device__ float    g_coef[BB * 2];
__device__ int      g_idx[BB * 2];
__device__ unsigned g_arrive[BB];      // per-batch stage-1 arrivals (reset by gater)
__device__ unsigned g_flag[BB];        // per-batch gating-done flags (reset by last finisher)
__device__ unsigned g_done[BB];        // per-batch stage-2 completion counters

typedef unsigned long long u64;

__device__ __forceinline__ void fma2(u64& d, u64 a, u64 b) {
    asm("fma.rn.f32x2 %0, %1, %2, %0;" : "+l"(d) : "l"(a), "l"(b));
}
__device__ __forceinline__ float lo2(u64 v) { return __uint_as_float((unsigned)(v & 0xffffffffull)); }
__device__ __forceinline__ float hi2(u64 v) { return __uint_as_float((unsigned)(v >> 32)); }

__device__ __forceinline__ void stcs4(float* p, float4 v) {
    asm volatile("st.global.cs.v4.f32 [%0], {%1, %2, %3, %4};"
                 :: "l"(p), "f"(v.x), "f"(v.y), "f"(v.z), "f"(v.w));
}

// ------------------------------------------------------------------
// Fused persistent kernel with PER-BATCH barriers.
// 512 CTAs, 256 thr, hard 64-reg cap (launch_bounds(256,4)):
// 4 CTAs/SM x 148 SMs = 592 >= 512 -> all CTAs wave-1 resident,
// so per-batch flag spins cannot deadlock.
//   stage 1: column sums of this CTA's 32 rows (DRAM read)
//   128th arriver of batch b: gates batch b, releases g_flag[b]
//   stage 2: select+project on the same rows (L2-hot) — batches
//            that gate early WRITE while late batches still READ.
// ------------------------------------------------------------------
#define TOKB 32
#define TPW  4

__global__ void __launch_bounds__(256, 4) fused_moe(const float* __restrict__ x,
                                                    const float* __restrict__ lora_A,
                                                    const float* __restrict__ lora_B,
                                                    const float* __restrict__ gate_w,
                                                    const float* __restrict__ gate_b,
                                                    float* __restrict__ out) {
    __shared__ float    A2[2 * IND];    // 8 KB : selected experts' A rows
    __shared__ float2   cs[TOKB];
    __shared__ float    dots[EE];
    __shared__ unsigned s_last;
    __shared__ int2     s_ix;
    __shared__ float2   s_cf;

    const int tid  = threadIdx.x;
    const int w    = tid >> 5;
    const int lane = tid & 31;
    const int b       = blockIdx.x >> 7;            // 128 CTAs per batch
    const int tokbase = (blockIdx.x & 127) * TOKB;

    // ================= stage 1: column sums (proven) =====================
    {
        const float* xp = x + ((size_t)b * SSEQ + tokbase) * IND + tid * 4;
        float4 a4 = make_float4(0.f, 0.f, 0.f, 0.f);
        #pragma unroll 8
        for (int r = 0; r < TOKB; ++r) {
            float4 v = *(const float4*)(xp + (size_t)r * IND);
            a4.x += v.x; a4.y += v.y; a4.z += v.z; a4.w += v.w;
        }
        float* dst = &g_seg[b * IND + tid * 4];
        atomicAdd(dst + 0, a4.x);
        atomicAdd(dst + 1, a4.y);
        atomicAdd(dst + 2, a4.z);
        atomicAdd(dst + 3, a4.w);
    }

    // ============ per-batch arrive; 128th arriver gates batch b ==========
    __syncthreads();
    if (tid == 0) {
        unsigned old;
        asm volatile("atom.acq_rel.gpu.global.add.u32 %0, [%1], 1;"
                     : "=r"(old) : "l"(&g_arrive[b]) : "memory");
        s_last = (old == (unsigned)(CPB - 1)) ? 1u : 0u;
    }
    __syncthreads();

    if (s_last) {
        // ---- gating for THIS batch only: warp w owns expert w ----
        {
            float s = 0.f;
            #pragma unroll
            for (int i = 0; i < 8; ++i) {
                int k = lane * 4 + i * 128;
                float4 a = *(const float4*)&g_seg[b * IND + k];
                float4 g = *(const float4*)&gate_w[w * IND + k];
                s += a.x * g.x + a.y * g.y + a.z * g.z + a.w * g.w;
            }
            #pragma unroll
            for (int o = 16; o; o >>= 1) s += __shfl_xor_sync(0xffffffffu, s, o);
            if (lane == 0) dots[w] = s * (1.0f / (float)SSEQ) + gate_b[w];
        }
        __syncthreads();

        // zero this batch's g_seg slice for the next replay (256 float4)
        ((float4*)&g_seg[b * IND])[tid] = make_float4(0.f, 0.f, 0.f, 0.f);

        if (tid == 0) {
            float l[EE]; float mx = -1e30f;
            #pragma unroll
            for (int i = 0; i < EE; ++i) { l[i] = dots[i]; mx = fmaxf(mx, l[i]); }
            float sum = 0.f;
            #pragma unroll
            for (int i = 0; i < EE; ++i) { l[i] = expf(l[i] - mx); sum += l[i]; }
            int i0 = 0;
            #pragma unroll
            for (int i = 1; i < EE; ++i) if (l[i] > l[i0]) i0 = i;   // ties -> lowest idx
            int i1 = (i0 == 0) ? 1 : 0;
            #pragma unroll
            for (int i = 0; i < EE; ++i) if (i != i0 && l[i] > l[i1]) i1 = i;
            g_idx[b * 2] = i0;  g_idx[b * 2 + 1] = i1;
            float f = LSCALE / sum;
            g_coef[b * 2]     = l[i0] * f;
            g_coef[b * 2 + 1] = l[i1] * f;
            g_arrive[b] = 0;                        // safe: all 128 arrived
        }
        __syncthreads();                            // coef/idx + zeroing done
        if (tid == 0)
            asm volatile("st.release.gpu.global.u32 [%0], %1;"
                         :: "l"(&g_flag[b]), "r"(1u) : "memory");
    } else {
        if (tid == 0) {
            unsigned f = 0;
            do {
                __nanosleep(64);
                asm volatile("ld.acquire.gpu.global.u32 %0, [%1];"
                             : "=r"(f) : "l"(&g_flag[b]) : "memory");
            } while (f == 0);
        }
    }
    __syncthreads();

    // broadcast gate results via shared (tid0 holds the acquire edge)
    if (tid == 0) {
        s_ix = *(const int2*)&g_idx[b * 2];
        s_cf = *(const float2*)&g_coef[b * 2];
    }
    __syncthreads();
    const int   e0 = s_ix.x, e1 = s_ix.y;
    const float w0 = s_cf.x, w1 = s_cf.y;

    // ================= stage 2: select + project (R13-proven) ============
    {
        float4 a0 = *(const float4*)&lora_A[e0 * IND + tid * 4];
        float4 a1 = *(const float4*)&lora_A[e1 * IND + tid * 4];
        *(float4*)&A2[tid * 4]       = a0;
        *(float4*)&A2[IND + tid * 4] = a1;
    }
    __syncthreads();

    u64 acc0[TPW], acc1[TPW];
    #pragma unroll
    for (int t = 0; t < TPW; ++t) { acc0[t] = 0ull; acc1[t] = 0ull; }

    const float* xw = x + ((size_t)(b * SSEQ + tokbase + w * TPW)) * IND;

    #pragma unroll 4
    for (int c = 0; c < 8; ++c) {
        const int koff = c * 128 + lane * 4;
        double2 a0v = *(const double2*)&A2[koff];
        double2 a1v = *(const double2*)&A2[IND + koff];
        u64 a0lo = __double_as_longlong(a0v.x), a0hi = __double_as_longlong(a0v.y);
        u64 a1lo = __double_as_longlong(a1v.x), a1hi = __double_as_longlong(a1v.y);
        #pragma unroll
        for (int t = 0; t < TPW; ++t) {
            double2 xv = *(const double2*)(xw + (size_t)t * IND + koff);
            u64 xlo = __double_as_longlong(xv.x);
            u64 xhi = __double_as_longlong(xv.y);
            fma2(acc0[t], xlo, a0lo);
            fma2(acc0[t], xhi, a0hi);
            fma2(acc1[t], xlo, a1lo);
            fma2(acc1[t], xhi, a1hi);
        }
    }

    #pragma unroll
    for (int t = 0; t < TPW; ++t) {
        float h0 = lo2(acc0[t]) + hi2(acc0[t]);
        float h1 = lo2(acc1[t]) + hi2(acc1[t]);
        #pragma unroll
        for (int off = 16; off; off >>= 1) {
            h0 += __shfl_xor_sync(0xffffffffu, h0, off);
            h1 += __shfl_xor_sync(0xffffffffu, h1, off);
        }
        if (lane == 0) cs[w * TPW + t] = make_float2(w0 * h0, w1 * h1);
    }

    // B rows register-resident — loaded after phase A
    float4 B0 = *(const float4*)&lora_B[e0 * OUTD + tid * 4];
    float4 B1 = *(const float4*)&lora_B[e1 * OUTD + tid * 4];
    __syncthreads();

    float* ob = out + ((size_t)b * SSEQ + tokbase) * OUTD + tid * 4;
    #pragma unroll 4
    for (int i = 0; i < TOKB; ++i) {
        float2 cc = cs[i];
        float4 v;
        v.x = cc.x * B0.x + cc.y * B1.x;
        v.y = cc.x * B0.y + cc.y * B1.y;
        v.z = cc.x * B0.z + cc.y * B1.z;
        v.w = cc.x * B0.w + cc.y * B1.w;
        stcs4(ob + (size_t)i * OUTD, v);
    }

    // ---- per-batch flag reset for the next graph replay ----
    __syncthreads();
    if (tid == 0) {
        unsigned old;
        asm volatile("atom.acq_rel.gpu.global.add.u32 %0, [%1], 1;"
                     : "=r"(old) : "l"(&g_done[b]) : "memory");
        if (old == (unsigned)(CPB - 1)) {
            g_flag[b] = 0;
            g_done[b] = 0;
        }
    }
}

// ------------------------------------------------------------------
extern "C" void kernel_launch(void* const* d_in, const int* in_sizes, int n_in,
                              void* d_out, int out_size) {
    const float* x      = (const float*)d_in[0];
    const float* lora_A = (const float*)d_in[1];
    const float* lora_B = (const float*)d_in[2];
    const float* gate_w = (const float*)d_in[3];
    const float* gate_b = (const float*)d_in[4];
    float* out = (float*)d_out;

    fused_moe<<<GRID, 256>>>(x, lora_A, lora_B, gate_w, gate_b, out);
}